// round 16
// baseline (speedup 1.0000x reference)
#include <cuda_runtime.h>
#include <cstdint>

// SpanRepresentation: out[b, span, :] = concat(x[b, start], x[b, end], width_emb[w-1])
//   x: (16, 512, 768) f32, width_emb: (8, 64) f32, L = 512
//   spans: width w=1..8, start s=0..L-w  -> 4068 spans
//   out: (16, 4068, 1600) f32
//
// R15: persistent-CTA variant of the converged R9 config. 592 CTAs
// (148 SMs x occ 4) x 512 threads; each CTA grid-strides over the
// 1017*16 = 16272 span-blocks (4 spans per block, one per 128-thread
// quad). Eliminates ~27 wave transitions and keeps per-SM read/write
// streams continuous (iteration i+1 loads overlap iteration i stores).
// Data path identical to R9: float4 __ldg + __stcs, branchless width
// decode.

namespace {

constexpr int B  = 16;
constexpr int L  = 512;
constexpr int D  = 768;
constexpr int WD = 64;

// cumulative span offsets per width index wi (0-based): off[wi] = wi*L - wi*(wi-1)/2
constexpr int OFF1 = 1 * L - 0;            // 512
constexpr int OFF2 = 2 * L - 1;            // 1023
constexpr int OFF3 = 3 * L - 3;            // 1533
constexpr int OFF4 = 4 * L - 6;            // 2042
constexpr int OFF5 = 5 * L - 10;           // 2550
constexpr int OFF6 = 6 * L - 15;           // 3057
constexpr int OFF7 = 7 * L - 21;           // 3563
constexpr int NSPANS = 8 * L - 28;         // 4068 (divisible by 4)

constexpr int D4    = D / 4;               // 192 float4 per x row
constexpr int WD4   = WD / 4;              // 16 float4 per width_emb row
constexpr int ROW4  = 2 * D4 + WD4;        // 400 float4 per output row (6400 B)

constexpr int THREADS = 512;               // four 128-thread quads, one span each
constexpr int SPANS_PER_BLK = 4;
constexpr int SBLK_PER_BATCH = NSPANS / SPANS_PER_BLK;   // 1017
constexpr int TOTAL_BLKS = SBLK_PER_BATCH * B;           // 16272

constexpr int GRID = 592;                  // 148 SMs x 4 resident CTAs

} // namespace

__global__ __launch_bounds__(THREADS, 4)
void span_repr_kernel(const float4* __restrict__ x,
                      const float4* __restrict__ wemb,
                      float4* __restrict__ out)
{
    const int quad = threadIdx.x >> 7;            // 0..3 (warp-aligned split)
    const int t    = threadIdx.x & 127;           // lane within the quad

    for (int blk = blockIdx.x; blk < TOTAL_BLKS; blk += GRID) {
        const int b    = blk / SBLK_PER_BATCH;           // div-by-const -> mul.hi
        const int sblk = blk - b * SBLK_PER_BATCH;
        const int span = sblk * SPANS_PER_BLK + quad;    // 0..NSPANS-1

        // width index via 7 compares against constexpr cumulative offsets
        int wi = 0;
        if (span >= OFF1) wi = 1;
        if (span >= OFF2) wi = 2;
        if (span >= OFF3) wi = 3;
        if (span >= OFF4) wi = 4;
        if (span >= OFF5) wi = 5;
        if (span >= OFF6) wi = 6;
        if (span >= OFF7) wi = 7;

        int off;
        switch (wi) {
            case 0: off = 0;    break;
            case 1: off = OFF1; break;
            case 2: off = OFF2; break;
            case 3: off = OFF3; break;
            case 4: off = OFF4; break;
            case 5: off = OFF5; break;
            case 6: off = OFF6; break;
            default: off = OFF7; break;
        }
        const int s = span - off;          // start position
        const int e = s + wi;              // end position (= s + w - 1)

        const float4* __restrict__ xs = x + (size_t)(b * L + s) * D4;
        const float4* __restrict__ xe = x + (size_t)(b * L + e) * D4;
        const float4* __restrict__ we = wemb + wi * WD4;
        float4* __restrict__ o = out + (size_t)(b * NSPANS + span) * (size_t)ROW4;

        // 400 float4 per row; 128 threads per quad -> 4 strided passes
        #pragma unroll
        for (int j = 0; j < 4; ++j) {
            const int idx = t + j * 128;
            if (idx < D4) {
                __stcs(o + idx, __ldg(xs + idx));
            } else if (idx < 2 * D4) {
                __stcs(o + idx, __ldg(xe + (idx - D4)));
            } else if (idx < ROW4) {
                __stcs(o + idx, __ldg(we + (idx - 2 * D4)));
            }
        }
        // no barrier needed: iterations are independent; scoreboard
        // overlaps next loads with outstanding streaming stores
    }
}

extern "C" void kernel_launch(void* const* d_in, const int* in_sizes, int n_in,
                              void* d_out, int out_size)
{
    const float4* x    = (const float4*)d_in[0];   // (16, 512, 768) f32
    const float4* wemb = (const float4*)d_in[1];   // (8, 64) f32
    // d_in[2] = batch_max_seq_len (== 512, fixed for this instance) — unused
    float4* out = (float4*)d_out;

    span_repr_kernel<<<GRID, THREADS>>>(x, wemb, out);
}